// round 15
// baseline (speedup 1.0000x reference)
#include <cuda_runtime.h>
#include <cuda_fp16.h>
#include <math.h>
#include <stdint.h>

#define D_MODEL 1024
#define D_STATE 128
#define SEQ_LEN 4096
#define BATCH   4
#define ROWS    (BATCH * SEQ_LEN)        // 16384
#define LN_EPS  1e-3f
#define NPROJ   384
#define ACTW    1152                     // [xn(1024) | ysc(128)]
#define KCAT    1152
#define SK_W4   12
#define SK_WC   2

// ---------------- scratch (allocation-free: __device__ globals) ----------------
__device__ __half g_act [(size_t)ROWS * ACTW];
__device__ float  g_proj[(size_t)ROWS * NPROJ];
__device__ __half g_WinA [(size_t)D_MODEL * 2 * D_MODEL];
__device__ __half g_WcatA[(size_t)KCAT    * 2 * D_MODEL];
__device__ __half g_WpkB [(size_t)NPROJ   * 2 * D_MODEL];
__device__ __half g_WoutB[(size_t)D_MODEL * 2 * D_MODEL];
__device__ float  g_W4part [(size_t)SK_W4 * NPROJ   * D_MODEL];
__device__ float  g_WcatPart[(size_t)SK_WC * D_MODEL * KCAT];
__device__ __half g_W4  [(size_t)NPROJ   * D_MODEL];
__device__ __half g_Wcat[(size_t)D_MODEL * KCAT];
__device__ float g_b4[NPROJ];
__device__ float g_b5[D_MODEL];
__device__ float g_carry[BATCH * 64 * D_STATE];

// ---------------- helpers ----------------
__device__ __forceinline__ uint32_t cvta_smem(const void* p) {
    uint32_t a;
    asm("{ .reg .u64 t; cvta.to.shared.u64 t, %1; cvt.u32.u64 %0, t; }" : "=r"(a) : "l"(p));
    return a;
}
__device__ __forceinline__ uint32_t pack_h2(__half a, __half b) {
    __half2 t; t.x = a; t.y = b;
    return *reinterpret_cast<uint32_t*>(&t);
}
__device__ __forceinline__ void split_store(__half* dst, size_t base, int K, int k, float w) {
    __half hi = __float2half_rn(w);
    __half lo = __float2half_rn(w - __half2float(hi));
    dst[base + k]     = hi;
    dst[base + K + k] = lo;
}

#define MMA_F16(d, a, b) \
    asm volatile( \
        "mma.sync.aligned.m16n8k16.row.col.f32.f16.f16.f32 " \
        "{%0,%1,%2,%3}, {%4,%5,%6,%7}, {%8,%9}, {%0,%1,%2,%3};" \
        : "+f"((d)[0]), "+f"((d)[1]), "+f"((d)[2]), "+f"((d)[3]) \
        : "r"((a)[0]), "r"((a)[1]), "r"((a)[2]), "r"((a)[3]), \
          "r"((b)[0]), "r"((b)[1]))

#define LDSM_X4(r, addr) \
    asm volatile("ldmatrix.sync.aligned.m8n8.x4.shared.b16 {%0,%1,%2,%3}, [%4];" \
        : "=r"((r)[0]), "=r"((r)[1]), "=r"((r)[2]), "=r"((r)[3]) : "r"(addr))

// ---------------- LayerNorm -> fp16 into g_act (stride ACTW) ----------------
__global__ __launch_bounds__(256) void ln_h_kernel(
    const float* __restrict__ x, const float* __restrict__ gamma,
    const float* __restrict__ beta, __half* __restrict__ act)
{
    int row = blockIdx.x;
    int tid = threadIdx.x;
    const float4* xr = (const float4*)(x + (size_t)row * D_MODEL);
    float4 v = xr[tid];

    float s  = v.x + v.y + v.z + v.w;
    float sq = v.x*v.x + v.y*v.y + v.z*v.z + v.w*v.w;
    #pragma unroll
    for (int o = 16; o > 0; o >>= 1) {
        s  += __shfl_xor_sync(0xffffffffu, s,  o);
        sq += __shfl_xor_sync(0xffffffffu, sq, o);
    }
    __shared__ float sh_s[8], sh_q[8];
    int wid = tid >> 5, lid = tid & 31;
    if (lid == 0) { sh_s[wid] = s; sh_q[wid] = sq; }
    __syncthreads();
    if (wid == 0) {
        float a = (lid < 8) ? sh_s[lid] : 0.f;
        float b = (lid < 8) ? sh_q[lid] : 0.f;
        #pragma unroll
        for (int o = 4; o > 0; o >>= 1) {
            a += __shfl_xor_sync(0xffffffffu, a, o);
            b += __shfl_xor_sync(0xffffffffu, b, o);
        }
        if (lid == 0) { sh_s[0] = a; sh_q[0] = b; }
    }
    __syncthreads();
    float mu   = sh_s[0] * (1.0f / D_MODEL);
    float var  = sh_q[0] * (1.0f / D_MODEL) - mu * mu;
    float rstd = rsqrtf(var + LN_EPS);

    float4 gv = ((const float4*)gamma)[tid];
    float4 bv = ((const float4*)beta)[tid];
    float o0 = (v.x - mu) * rstd * gv.x + bv.x;
    float o1 = (v.y - mu) * rstd * gv.y + bv.y;
    float o2 = (v.z - mu) * rstd * gv.z + bv.z;
    float o3 = (v.w - mu) * rstd * gv.w + bv.w;

    uint2 hv = make_uint2(pack_h2(__float2half_rn(o0), __float2half_rn(o1)),
                          pack_h2(__float2half_rn(o2), __float2half_rn(o3)));
    *(uint2*)(act + (size_t)row * ACTW + tid * 4) = hv;
}

// ---------------- A-side preps (coalesced, elementwise) ----------------
__global__ void prepA_win(const float* __restrict__ W_in, __half* __restrict__ WinA)
{
    int idx = blockIdx.x * blockDim.x + threadIdx.x;
    if (idx >= D_MODEL * D_MODEL) return;
    int m = idx >> 10, k = idx & 1023;
    split_store(WinA, (size_t)m * 2 * D_MODEL, D_MODEL, k, W_in[idx]);
}

__global__ void prepA_cat(const float* __restrict__ W_in, const float* __restrict__ D,
                          const float* __restrict__ W_so, __half* __restrict__ WcatA)
{
    int idx = blockIdx.x * blockDim.x + threadIdx.x;
    if (idx >= KCAT * D_MODEL) return;
    int m = idx >> 10, j = idx & 1023;
    float w = (m < D_MODEL) ? (W_in[(size_t)m * D_MODEL + j] * D[j])
                            : W_so[(size_t)(m - D_MODEL) * D_MODEL + j];
    split_store(WcatA, (size_t)m * 2 * D_MODEL, D_MODEL, j, w);
}

// ---------------- B-side preps: tiled transpose + split ----------------
__global__ __launch_bounds__(256) void tsplit_pk(
    const float* __restrict__ Wxs, const float* __restrict__ WB,
    const float* __restrict__ WC, __half* __restrict__ dst)
{
    __shared__ float t[32][33];
    int tx = threadIdx.x, ty = threadIdx.y;
    int n0 = blockIdx.x * 32, k0 = blockIdx.y * 32;
    #pragma unroll
    for (int i = 0; i < 4; i++) {
        int n = n0 + tx;
        int c = n & 127;
        const float* src = (n < 128) ? Wxs : ((n < 256) ? WB : WC);
        t[ty + 8 * i][tx] = src[(size_t)(k0 + ty + 8 * i) * 128 + c];
    }
    __syncthreads();
    #pragma unroll
    for (int i = 0; i < 4; i++) {
        int n = n0 + ty + 8 * i, k = k0 + tx;
        split_store(dst, (size_t)n * 2 * D_MODEL, D_MODEL, k, t[tx][ty + 8 * i]);
    }
}

__global__ __launch_bounds__(256) void tsplit_out(
    const float* __restrict__ W, __half* __restrict__ dst)
{
    __shared__ float t[32][33];
    int tx = threadIdx.x, ty = threadIdx.y;
    int n0 = blockIdx.x * 32, k0 = blockIdx.y * 32;
    #pragma unroll
    for (int i = 0; i < 4; i++)
        t[ty + 8 * i][tx] = W[(size_t)(k0 + ty + 8 * i) * D_MODEL + n0 + tx];
    __syncthreads();
    #pragma unroll
    for (int i = 0; i < 4; i++) {
        int n = n0 + ty + 8 * i, k = k0 + tx;
        split_store(dst, (size_t)n * 2 * D_MODEL, D_MODEL, k, t[tx][ty + 8 * i]);
    }
}

// ---------------- bias reductions (block per output) ----------------
__global__ __launch_bounds__(128) void bias4_k(const float* __restrict__ b_in,
                        const float* __restrict__ W_xs, const float* __restrict__ W_B,
                        const float* __restrict__ bB,  const float* __restrict__ W_C,
                        const float* __restrict__ bC,  float* __restrict__ b4)
{
    __shared__ float sh[4];
    int n = blockIdx.x, tid = threadIdx.x;
    const float* W; const float* badd = nullptr; int c = n;
    if (n < 128)      { W = W_xs; }
    else if (n < 256) { W = W_B; c = n - 128; badd = bB; }
    else              { W = W_C; c = n - 256; badd = bC; }
    float acc = 0.f;
    for (int j = tid; j < D_MODEL; j += 128) acc += b_in[j] * W[(size_t)j * 128 + c];
    #pragma unroll
    for (int o = 16; o > 0; o >>= 1) acc += __shfl_xor_sync(0xffffffffu, acc, o);
    if ((tid & 31) == 0) sh[tid >> 5] = acc;
    __syncthreads();
    if (tid == 0) {
        float t = sh[0] + sh[1] + sh[2] + sh[3];
        b4[n] = t + (badd ? badd[c] : 0.f);
    }
}

__global__ __launch_bounds__(128) void bias5_k(const float* __restrict__ b_in,
                        const float* __restrict__ D, const float* __restrict__ W_out,
                        const float* __restrict__ b_out, float* __restrict__ b5)
{
    __shared__ float sh[4];
    int n = blockIdx.x, tid = threadIdx.x;
    float acc = 0.f;
    for (int j = tid; j < D_MODEL; j += 128)
        acc += b_in[j] * D[j] * W_out[(size_t)j * D_MODEL + n];
    #pragma unroll
    for (int o = 16; o > 0; o >>= 1) acc += __shfl_xor_sync(0xffffffffu, acc, o);
    if ((tid & 31) == 0) sh[tid >> 5] = acc;
    __syncthreads();
    if (tid == 0) b5[n] = sh[0] + sh[1] + sh[2] + sh[3] + b_out[n];
}

// ---------------- precompute GEMM (3-term fp16 dual split, split-K -> fp32 partials) ----------------
#define PBM 128
#define PBN 64
#define PRSB 80
#define PTILEA (PBM * PRSB)
#define PSTAGE ((PBM + PBN) * PRSB)
#define PGSM (3 * PSTAGE)

__global__ __launch_bounds__(256, 2)
void pgemm(const __half* __restrict__ A, const __half* __restrict__ B, int K,
           float* __restrict__ Wpart, int Nc, int ldw, int chunks_per)
{
    extern __shared__ __align__(128) char smem[];
    const int tid  = threadIdx.x;
    const int warp = tid >> 5, lane = tid & 31;
    const int wm = warp & 1, wn = warp >> 1;
    const int m0 = blockIdx.y * PBM, n0 = blockIdx.x * PBN;
    const int z  = blockIdx.z;
    const int c0 = z * chunks_per;
    const uint32_t smem_base = cvta_smem(smem);

    const int KB = K / 32;
    const size_t row_bytes = (size_t)K * 4;
    const __half* Ab = A + (size_t)m0 * 2 * K;
    const __half* Bb = B + (size_t)n0 * 2 * K;

    float acc[4][2][4];
    #pragma unroll
    for (int i = 0; i < 4; i++)
        #pragma unroll
        for (int j = 0; j < 2; j++)
            #pragma unroll
            for (int e = 0; e < 4; e++) acc[i][j][e] = 0.f;

    auto load_stage = [&](int sk, int buf) {
        const uint32_t sb = smem_base + buf * PSTAGE;
        int lkA = (sk < 2 * KB) ? sk : sk - 2 * KB;   // A: [hi|lo|hi]
        int lkB = (sk < KB)     ? sk : sk - KB;       // B: [hi|hi|lo]
        const size_t kbA = (size_t)lkA * 64;
        const size_t kbB = (size_t)lkB * 64;
        #pragma unroll
        for (int j = 0; j < 2; j++) {
            int chunk = tid + j * 256;
            int row = chunk >> 2, cb = chunk & 3;
            const char* ga = (const char*)Ab + (size_t)row * row_bytes + kbA + cb * 16;
            asm volatile("cp.async.cg.shared.global [%0], [%1], 16;"
                         :: "r"(sb + row * PRSB + cb * 16), "l"(ga));
        }
        {
            int row = tid >> 2, cb = tid & 3;
            const char* gb = (const char*)Bb + (size_t)row * row_bytes + kbB + cb * 16;
            asm volatile("cp.async.cg.shared.global [%0], [%1], 16;"
                         :: "r"(sb + PTILEA + row * PRSB + cb * 16), "l"(gb));
        }
        asm volatile("cp.async.commit_group;");
    };

    #pragma unroll
    for (int s = 0; s < 2; s++) load_stage(c0 + s, s);

    const uint32_t lrow = (lane & 15);
    const uint32_t lkb  = (lane >> 4) * 16;

    for (int i = 0; i < chunks_per; i++) {
        asm volatile("cp.async.wait_group 1;");
        __syncthreads();
        int nxt = i + 2;
        if (nxt < chunks_per) load_stage(c0 + nxt, nxt % 3);
        else                  asm volatile("cp.async.commit_group;");

        const uint32_t sb = smem_base + (i % 3) * PSTAGE;
        const uint32_t abase = sb + (wm * 64) * PRSB;
        const uint32_t bbase = sb + PTILEA + (wn * 16) * PRSB;

        #pragma unroll
        for (int ks = 0; ks < 2; ks++) {
            uint32_t Af[4][4], Bf[4];
            #pragma unroll
            for (int mt = 0; mt < 4; mt++)
                LDSM_X4(Af[mt], abase + (mt * 16 + lrow) * PRSB + ks * 32 + lkb);
            LDSM_X4(Bf, bbase + lrow * PRSB + ks * 32 + lkb);

            #pragma unroll
            for (int mt = 0; mt < 4; mt++) {
                #pragma unroll
                for (int nt = 0; nt < 2; nt++) {
                    uint32_t b2[2] = { Bf[nt], Bf[nt + 2] };
                    MMA_F16(acc[mt][nt], Af[mt], b2);
                }
            }
        }
    }

    float* Wp = Wpart + (size_t)z * Nc * ldw;
    const int groupID = lane >> 2, tig = lane & 3;
    #pragma unroll
    for (int mt = 0; mt < 4; mt++) {
        #pragma unroll
        for (int nt = 0; nt < 2; nt++) {
            int r0 = m0 + wm * 64 + mt * 16 + groupID;
            int c0c = n0 + wn * 16 + nt * 8 + tig * 2;
            #pragma unroll
            for (int e = 0; e < 4; e++) {
                int r = r0 + (e >> 1) * 8;
                int c = c0c + (e & 1);
                Wp[(size_t)c * ldw + r] = acc[mt][nt][e];
            }
        }
    }
}

// ---------------- reduce partials -> fp16 weight ----------------
__global__ void reduce_quant(const float* __restrict__ part, int S, size_t plane,
                             __half* __restrict__ dst, int n)
{
    int idx = blockIdx.x * blockDim.x + threadIdx.x;
    if (idx >= n) return;
    float s = 0.f;
    for (int z = 0; z < S; z++) s += part[(size_t)z * plane + idx];
    dst[idx] = __float2half_rn(s);
}

// ---------------- big GEMM: C[M,Nc] = A_fp16[M,K](lda) @ W_fp16[Nc,ldb(.K slice)]^T ----------------
#define BM 128
#define BN 128
#define RSB 80
#define TILE_B (BM * RSB)
#define STAGE  (2 * TILE_B)
#define GSM    (4 * STAGE)                       // 81920

template<bool HAS_BIAS, bool HAS_RES>
__global__ __launch_bounds__(256, 2)
void bgemm(const __half* __restrict__ A, int lda, const __half* __restrict__ Bw,
           int K, int ldb, int Nc, float* __restrict__ Cf,
           const float* __restrict__ bias, const float* __restrict__ res)
{
    extern __shared__ __align__(128) char smem[];
    const int tid  = threadIdx.x;
    const int warp = tid >> 5, lane = tid & 31;
    const int wm = warp & 1, wn = warp >> 1;
    const int m0 = blockIdx.y * BM, n0 = blockIdx.x * BN;
    const uint32_t smem_base = cvta_smem(smem);

    const int NKP = K / 32;
    const size_t arow_bytes = (size_t)lda * 2;
    const size_t brow_bytes = (size_t)ldb * 2;
    const __half* Ab = A  + (size_t)m0 * lda;
    const __half* Bb = Bw + (size_t)n0 * ldb;

    float acc[4][4][4];
    #pragma unroll
    for (int i = 0; i < 4; i++)
        #pragma unroll
        for (int j = 0; j < 4; j++)
            #pragma unroll
            for (int e = 0; e < 4; e++) acc[i][j][e] = 0.f;

    auto load_stage = [&](int sk, int buf) {
        const uint32_t sb = smem_base + buf * STAGE;
        const size_t kb = (size_t)sk * 64;
        #pragma unroll
        for (int j = 0; j < 2; j++) {
            int chunk = tid + j * 256;
            int row = chunk >> 2, cb = chunk & 3;
            const char* ga = (const char*)Ab + (size_t)row * arow_bytes + kb + cb * 16;
            asm volatile("cp.async.cg.shared.global [%0], [%1], 16;"
                         :: "r"(sb + row * RSB + cb * 16), "l"(ga));
        }
        #pragma unroll
        for (int j = 0; j < 2; j++) {
            int chunk = tid + j * 256;
            int row = chunk >> 2, cb = chunk & 3;
            const char* gb = (const char*)Bb + (size_t)row * brow_bytes + kb + cb * 16;
            asm volatile("cp.async.cg.shared.global [%0], [%1], 16;"
                         :: "r"(sb + TILE_B + row * RSB + cb * 16), "l"(gb));
        }
        asm volatile("cp.async.commit_group;");
    };

    #pragma unroll
    for (int s = 0; s < 3; s++) load_stage(s, s);

    const uint32_t lrow = (lane & 15);
    const uint32_t lkb  = (lane >> 4) * 16;

    for (int i = 0; i < NKP; i++) {
        asm volatile("cp.async.wait_group 2;");
        __syncthreads();
        int nxt = i + 3;
        if (nxt < NKP) load_stage(nxt, nxt & 3);
        else           asm volatile("cp.async.commit_group;");

        const uint32_t sb = smem_base + (i & 3) * STAGE;
        const uint32_t abase = sb + (wm * 64) * RSB;
        const uint32_t bbase = sb + TILE_B + (wn * 32) * RSB;

        #pragma unroll
        for (int ks = 0; ks < 2; ks++) {
            uint32_t Af[4][4], Bf[2][4];
            #pragma unroll
            for (int mt = 0; mt < 4; mt++)
                LDSM_X4(Af[mt], abase + (mt * 16 + lrow) * RSB + ks * 32 + lkb);
            #pragma unroll
            for (int g = 0; g < 2; g++)
                LDSM_X4(Bf[g], bbase + (g * 16 + lrow) * RSB + ks * 32 + lkb);

            #pragma unroll
            for (int mt = 0; mt < 4; mt++)
                #pragma unroll
                for (int nt = 0; nt < 4; nt++) {
                    uint32_t b2[2] = { Bf[nt >> 1][nt & 1], Bf[nt >> 1][(nt & 1) + 2] };
                    MMA_F16(acc[mt][nt], Af[mt], b2);
                }
        }
    }
    __syncthreads();

    // ---- acc -> smem bounce -> fused coalesced epilogue ----
    float* stile = (float*)smem;               // [128][132]
    const int groupID = lane >> 2, tig = lane & 3;
    #pragma unroll
    for (int mt = 0; mt < 4; mt++) {
        int r0 = wm * 64 + mt * 16 + groupID;
        #pragma unroll
        for (int nt = 0; nt < 4; nt++) {
            int c = wn * 32 + nt * 8 + tig * 2;
            *(float2*)&stile[r0 * 132 + c]       = make_float2(acc[mt][nt][0], acc[mt][nt][1]);
            *(float2*)&stile[(r0 + 8) * 132 + c] = make_float2(acc[mt][nt][2], acc[mt][nt][3]);
        }
    }
    __syncthreads();

    float4 b4 = make_float4(0.f, 0.f, 0.f, 0.f);
    int col = n0 + lane * 4;
    if (HAS_BIAS) b4 = *(const float4*)(bias + col);

    #pragma unroll 4
    for (int rr = 0; rr < 16; rr++) {
        int r = warp * 16 + rr;
        int row = m0 + r;
        float4 v = *(float4*)&stile[r * 132 + lane * 4];
        if (HAS_BIAS) { v.x += b4.x; v.y += b4.y; v.z += b4.z; v.w += b4.w; }
        if (HAS_RES) {
            float4 r4 = *(const float4*)(res + (size_t)row * Nc + col);
            v.x += r4.x; v.y += r4.y; v.z += r4.z; v.w += r4.w;
        }
        *(float4*)(Cf + (size_t)row * Nc + col) = v;
    }
}

// ---------------- chunked scan (== FFT causal conv) ----------------
#define CHUNK 64
#define NCHUNK (SEQ_LEN / CHUNK)

__global__ __launch_bounds__(128) void scan1(const float* __restrict__ proj,
                                             const float* __restrict__ A_log,
                                             float* __restrict__ carry)
{
    int c = blockIdx.x, b = blockIdx.y, s = threadIdx.x;
    float lam = expf(-expf(A_log[s]));
    size_t row0 = (size_t)b * SEQ_LEN + c * CHUNK;
    float y = 0.f;
    #pragma unroll 8
    for (int t = 0; t < CHUNK; t++) {
        const float* p = proj + (row0 + t) * NPROJ;
        y = fmaf(lam, y, p[s] * p[128 + s]);
    }
    carry[(b * NCHUNK + c) * D_STATE + s] = y;
}

__global__ __launch_bounds__(128) void scan2(const float* __restrict__ A_log,
                                             float* __restrict__ carry)
{
    int b = blockIdx.x, s = threadIdx.x;
    float lam64 = expf(-expf(A_log[s]) * (float)CHUNK);
    float S = 0.f;
    for (int c = 0; c < NCHUNK; c++) {
        size_t i = (size_t)(b * NCHUNK + c) * D_STATE + s;
        float f = carry[i];
        carry[i] = S;
        S = fmaf(lam64, S, f);
    }
}

__global__ __launch_bounds__(128) void scan3(const float* __restrict__ proj,
                                             const float* __restrict__ A_log,
                                             const float* __restrict__ carry,
                                             __half* __restrict__ act)
{
    int c = blockIdx.x, b = blockIdx.y, s = threadIdx.x;
    float lam = expf(-expf(A_log[s]));
    float y = carry[(b * NCHUNK + c) * D_STATE + s];
    size_t row0 = (size_t)b * SEQ_LEN + c * CHUNK;
    #pragma unroll 4
    for (int t = 0; t < CHUNK; t++) {
        size_t row = row0 + t;
        const float* p = proj + row * NPROJ;
        y = fmaf(lam, y, p[s] * p[128 + s]);
        act[row * ACTW + D_MODEL + s] = __float2half_rn(y * p[256 + s]);
    }
}

// ---------------- launch ----------------
extern "C" void kernel_launch(void* const* d_in, const int* in_sizes, int n_in,
                              void* d_out, int out_size)
{
    const float* x        = (const float*)d_in[0];
    const float* ln_gamma = (const float*)d_in[1];
    const float* ln_beta  = (const float*)d_in[2];
    const float* W_in     = (const float*)d_in[3];
    const float* b_in     = (const float*)d_in[4];
    const float* W_xs     = (const float*)d_in[5];
    const float* W_B      = (const float*)d_in[6];
    const float* b_B      = (const float*)d_in[7];
    const float* W_C      = (const float*)d_in[8];
    const float* b_C      = (const float*)d_in[9];
    const float* A_log    = (const float*)d_in[10];
    const float* Dv       = (const float*)d_in[11];
    const float* W_so     = (const float*)d_in[12];
    const float* W_out    = (const float*)d_in[13];
    const float* b_out    = (const float*)d_in[14];
    float* out = (float*)d_out;

    __half *p_act, *p_WinA, *p_WcatA, *p_WpkB, *p_WoutB, *p_W4, *p_Wcat;
    float *p_proj, *p_W4part, *p_WcatPart, *p_b4, *p_b5, *p_carry;
    cudaGetSymbolAddress((void**)&p_act,      g_act);
    cudaGetSymbolAddress((void**)&p_proj,     g_proj);
    cudaGetSymbolAddress((void**)&p_WinA,     g_WinA);
    cudaGetSymbolAddress((void**)&p_WcatA,    g_WcatA);
    cudaGetSymbolAddress((void**)&p_WpkB,     g_WpkB);
    cudaGetSymbolAddress((void**)&p_WoutB,    g_WoutB);
    cudaGetSymbolAddress((void**)&p_W4part,   g_W4part);
    cudaGetSymbolAddress((void**)&p_WcatPart, g_WcatPart);
    cudaGetSymbolAddress((void**)&p_W4,       g_W4);
    cudaGetSymbolAddress((void**)&p_Wcat,     g_Wcat);
    cudaGetSymbolAddress((void**)&p_b4,       g_b4);
    cudaGetSymbolAddress((void**)&p_b5,       g_b5);
    cudaGetSymbolAddress((void**)&p_carry,    g_carry);

    cudaFuncSetAttribute(pgemm, cudaFuncAttributeMaxDynamicSharedMemorySize, PGSM);
    cudaFuncSetAttribute(bgemm<true, false>, cudaFuncAttributeMaxDynamicSharedMemorySize, GSM);
    cudaFuncSetAttribute(bgemm<true, true >, cudaFuncAttributeMaxDynamicSharedMemorySize, GSM);
    cudaFuncSetAttribute(bgemm<false, true>, cudaFuncAttributeMaxDynamicSharedMemorySize, GSM);

    // ---- stream fork: precompute + out1 off the critical path ----
    cudaStream_t s2, s3;
    cudaStreamCreate(&s2);
    cudaStreamCreate(&s3);
    cudaEvent_t ev0, ev2, evLN, ev3;
    cudaEventCreateWithFlags(&ev0,  cudaEventDisableTiming);
    cudaEventCreateWithFlags(&ev2,  cudaEventDisableTiming);
    cudaEventCreateWithFlags(&evLN, cudaEventDisableTiming);
    cudaEventCreateWithFlags(&ev3,  cudaEventDisableTiming);

    cudaEventRecord(ev0, 0);
    cudaStreamWaitEvent(s2, ev0, 0);
    cudaStreamWaitEvent(s3, ev0, 0);

    // s2: W4 chain (needed before proj GEMM)
    prepA_win<<<(D_MODEL * D_MODEL + 255) / 256, 256, 0, s2>>>(W_in, p_WinA);
    tsplit_pk<<<dim3(NPROJ / 32, D_MODEL / 32), dim3(32, 8), 0, s2>>>(W_xs, W_B, W_C, p_WpkB);
    bias4_k<<<NPROJ, 128, 0, s2>>>(b_in, W_xs, W_B, b_B, W_C, b_C, p_b4);
    pgemm<<<dim3(NPROJ / PBN, D_MODEL / PBM, SK_W4), 256, PGSM, s2>>>(
        p_WinA, p_WpkB, D_MODEL, p_W4part, NPROJ, D_MODEL, (3 * D_MODEL / 32) / SK_W4);
    reduce_quant<<<(NPROJ * D_MODEL + 255) / 256, 256, 0, s2>>>(
        p_W4part, SK_W4, (size_t)NPROJ * D_MODEL, p_W4, NPROJ * D_MODEL);
    cudaEventRecord(ev2, s2);

    // s3: Wcat chain, then out1 = xn @ W3 + b5 + x (K=1024 prefix of Wcat)
    prepA_cat<<<(KCAT * D_MODEL + 255) / 256, 256, 0, s3>>>(W_in, Dv, W_so, p_WcatA);
    tsplit_out<<<dim3(D_MODEL / 32, D_MODEL / 32), dim3(32, 8), 0, s3>>>(W_out, p_WoutB);
    bias5_k<<<D_MODEL, 128, 0, s3>>>(b_in, Dv, W_out, b_out, p_b5);
    pgemm<<<dim3(D_MODEL / PBN, KCAT / PBM, SK_WC), 256, PGSM, s3>>>(
        p_WcatA, p_WoutB, D_MODEL, p_WcatPart, D_MODEL, KCAT, (3 * D_MODEL / 32) / SK_WC);
    reduce_quant<<<(D_MODEL * KCAT + 255) / 256, 256, 0, s3>>>(
        p_WcatPart, SK_WC, (size_t)D_MODEL * KCAT, p_Wcat, D_MODEL * KCAT);

    // main: LayerNorm -> act[:, 0:1024]
    ln_h_kernel<<<ROWS, 256>>>(x, ln_gamma, ln_beta, p_act);
    cudaEventRecord(evLN, 0);

    // s3 (cont.): out1 runs concurrently with proj + scan on main
    cudaStreamWaitEvent(s3, evLN, 0);
    bgemm<true, true><<<dim3(D_MODEL / BN, ROWS / BM), 256, GSM, s3>>>(
        p_act, ACTW, p_Wcat, D_MODEL, KCAT, D_MODEL, out, p_b5, x);
    cudaEventRecord(ev3, s3);

    // main: join W4 chain, then proj = xn @ W4 + b4
    cudaStreamWaitEvent(0, ev2, 0);
    bgemm<true, false><<<dim3(NPROJ / BN, ROWS / BM), 256, GSM>>>(
        p_act, ACTW, p_W4, D_MODEL, D_MODEL, NPROJ, p_proj, p_b4, nullptr);

    // main: chunked linear recurrence (== FFT causal conv) -> act[:, 1024:1152]
    scan1<<<dim3(NCHUNK, BATCH), 128>>>(p_proj, A_log, p_carry);
    scan2<<<BATCH, 128>>>(A_log, p_carry);
    scan3<<<dim3(NCHUNK, BATCH), 128>>>(p_proj, A_log, p_carry, p_act);

    // main: join out1, then out += ysc @ W1 (K=128 suffix of Wcat), in-place RMW
    cudaStreamWaitEvent(0, ev3, 0);
    bgemm<false, true><<<dim3(D_MODEL / BN, ROWS / BM), 256, GSM>>>(
        p_act + D_MODEL, ACTW, p_Wcat + D_MODEL, D_STATE, KCAT, D_MODEL, out, nullptr, out);

    cudaEventDestroy(ev0);
    cudaEventDestroy(ev2);
    cudaEventDestroy(evLN);
    cudaEventDestroy(ev3);
    cudaStreamDestroy(s2);
    cudaStreamDestroy(s3);
}